// round 1
// baseline (speedup 1.0000x reference)
#include <cuda_runtime.h>

// HawkesKT fused kernel for GB300 (sm_103a).
// Shapes: B=32, S=1024, D=64, NC=256.
// out[b][j-1] = sigmoid(qbias[q[b,j]] + cbias[c[b,j]] + sum_{i<j} alpha_ij * exp(-beta_ij * log5(|t_i-t_j|+1e-10)))
// alpha_ij = dot(a_inter[inters[b,i]], a_concept[c[b,j]])
// beta_ij  = clip(dot(b_inter[inters[b,i]], b_concept[c[b,j]]) + 1, 0, 10)

#define PAD 68  // padded smem row length (floats); 68*4 bytes keeps float4 alignment, avoids bank conflicts

__global__ __launch_bounds__(256)
void hawkes_kernel(
    const int*   __restrict__ concept_seq,      // [32,1024]
    const int*   __restrict__ question_seq,     // [32,1024]
    const int*   __restrict__ correctness_seq,  // [32,1024]
    const int*   __restrict__ time_seq,         // [32,1024]
    const float* __restrict__ a_inter,          // [512,64]
    const float* __restrict__ a_concept,        // [256,64]
    const float* __restrict__ b_inter,          // [512,64]
    const float* __restrict__ b_concept,        // [256,64]
    const float* __restrict__ q_bias,           // [10000,1]
    const float* __restrict__ c_bias,           // [256,1]
    float*       __restrict__ out)              // [32,1023]
{
    constexpr int SEQ = 1024;
    constexpr int DIM = 64;
    constexpr int NC  = 256;
    const float INV_LN5 = 0.62133497f;  // 1/ln(5), fp32

    extern __shared__ float sm[];
    float* As  = sm;                  // [64 d][PAD] alpha_inter tile (transposed: [d][i])
    float* Bs  = As + 64 * PAD;       // beta_inter tile [d][i]
    float* Cs  = Bs + 64 * PAD;       // alpha_concept tile [d][j]
    float* Ds  = Cs + 64 * PAD;       // beta_concept tile [d][j]
    float* tIs = Ds + 64 * PAD;       // [64] source times
    float* tJs = tIs + 64;            // [64] target times
    float* jred = tJs + 64;           // [64] per-j reduction

    const int jt  = blockIdx.x;       // j-tile 0..15
    const int b   = blockIdx.y;       // batch 0..31
    const int j0  = jt * 64;
    const int tid = threadIdx.x;
    const int ti  = tid >> 4;         // 0..15 (i sub-block)
    const int tj  = tid & 15;         // 0..15 (j sub-block)

    // ---- Load j-side tiles once (gather by concept) ----
    for (int e = tid; e < 64 * DIM; e += 256) {
        int j = e >> 6, d = e & 63;
        int cj = concept_seq[b * SEQ + j0 + j];
        Cs[d * PAD + j] = a_concept[cj * DIM + d];
        Ds[d * PAD + j] = b_concept[cj * DIM + d];
    }
    if (tid < 64) {
        tJs[tid]  = (float)time_seq[b * SEQ + j0 + tid];
        jred[tid] = 0.0f;
    }

    float jsum[4] = {0.f, 0.f, 0.f, 0.f};

    // ---- Loop over source (i) tiles, causal: i0 <= j0 ----
    for (int i0 = 0; i0 <= j0; i0 += 64) {
        __syncthreads();  // protect prior-iter reads & (first iter) j-side init

        // Load i-side tiles (gather by inter index)
        for (int e = tid; e < 64 * DIM; e += 256) {
            int i = e >> 6, d = e & 63;
            int g = b * SEQ + i0 + i;
            int inter = concept_seq[g] + correctness_seq[g] * NC;
            As[d * PAD + i] = a_inter[inter * DIM + d];
            Bs[d * PAD + i] = b_inter[inter * DIM + d];
        }
        if (tid < 64) tIs[tid] = (float)time_seq[b * SEQ + i0 + tid];
        __syncthreads();

        // ---- Dual 64x64x64 matmul, 4x4 register tile per thread ----
        float acca[4][4];
        float accb[4][4];
        #pragma unroll
        for (int x = 0; x < 4; x++)
            #pragma unroll
            for (int y = 0; y < 4; y++) { acca[x][y] = 0.f; accb[x][y] = 0.f; }

        #pragma unroll 4
        for (int d = 0; d < DIM; d++) {
            float4 av = *(const float4*)(As + d * PAD + ti * 4);
            float4 cv = *(const float4*)(Cs + d * PAD + tj * 4);
            float4 bv = *(const float4*)(Bs + d * PAD + ti * 4);
            float4 dv = *(const float4*)(Ds + d * PAD + tj * 4);
            float a_[4] = {av.x, av.y, av.z, av.w};
            float c_[4] = {cv.x, cv.y, cv.z, cv.w};
            float b_[4] = {bv.x, bv.y, bv.z, bv.w};
            float e_[4] = {dv.x, dv.y, dv.z, dv.w};
            #pragma unroll
            for (int ii = 0; ii < 4; ii++)
                #pragma unroll
                for (int jj = 0; jj < 4; jj++) {
                    acca[ii][jj] = fmaf(a_[ii], c_[jj], acca[ii][jj]);
                    accb[ii][jj] = fmaf(b_[ii], e_[jj], accb[ii][jj]);
                }
        }

        // ---- Elementwise + causal mask + accumulate over i ----
        const bool diag = (i0 == j0);
        float til[4];
        #pragma unroll
        for (int ii = 0; ii < 4; ii++) til[ii] = tIs[ti * 4 + ii];

        #pragma unroll
        for (int jj = 0; jj < 4; jj++) {
            float tv = tJs[tj * 4 + jj];
            #pragma unroll
            for (int ii = 0; ii < 4; ii++) {
                if (diag && (ti * 4 + ii >= tj * 4 + jj)) continue;  // strict i < j
                float dtv  = fabsf(til[ii] - tv);
                float lt   = __logf(dtv + 1e-10f) * INV_LN5;
                float beta = fminf(fmaxf(accb[ii][jj] + 1.0f, 0.0f), 10.0f);
                jsum[jj] += acca[ii][jj] * __expf(-beta * lt);
            }
        }
    }

    __syncthreads();
    #pragma unroll
    for (int jj = 0; jj < 4; jj++)
        atomicAdd(&jred[tj * 4 + jj], jsum[jj]);
    __syncthreads();

    // ---- Epilogue: bias + sigmoid, output drops j=0 ----
    if (tid < 64) {
        int j = j0 + tid;
        if (j > 0) {
            int q = question_seq[b * SEQ + j];
            int c = concept_seq[b * SEQ + j];
            float x = q_bias[q] + c_bias[c] + jred[tid];
            out[b * (SEQ - 1) + (j - 1)] = 1.0f / (1.0f + __expf(-x));
        }
    }
}

extern "C" void kernel_launch(void* const* d_in, const int* in_sizes, int n_in,
                              void* d_out, int out_size)
{
    (void)in_sizes; (void)n_in; (void)out_size;
    const int*   concept_seq     = (const int*)  d_in[0];
    const int*   question_seq    = (const int*)  d_in[1];
    const int*   correctness_seq = (const int*)  d_in[2];
    const int*   time_seq        = (const int*)  d_in[3];
    const float* a_inter         = (const float*)d_in[4];
    const float* a_concept       = (const float*)d_in[5];
    const float* b_inter         = (const float*)d_in[6];
    const float* b_concept       = (const float*)d_in[7];
    const float* q_bias          = (const float*)d_in[8];
    const float* c_bias          = (const float*)d_in[9];
    float* out = (float*)d_out;

    const int smem_bytes = (4 * 64 * PAD + 3 * 64) * (int)sizeof(float);  // 70400
    cudaFuncSetAttribute(hawkes_kernel,
                         cudaFuncAttributeMaxDynamicSharedMemorySize, smem_bytes);

    dim3 grid(16, 32);  // (j-tiles, batches)
    hawkes_kernel<<<grid, 256, smem_bytes>>>(
        concept_seq, question_seq, correctness_seq, time_seq,
        a_inter, a_concept, b_inter, b_concept, q_bias, c_bias, out);
}

// round 3
// speedup vs baseline: 3.0146x; 3.0146x over previous
#include <cuda_runtime.h>

// HawkesKT — table-collapsed formulation.
// alpha_ij = dot(a_inter[e_i], a_concept[c_j]) depends only on (e_i, c_j) in [0,512)x[0,256).
// Precompute G_alpha[c][e] and G_betap[c][e] = -clip(dot+1,0,10)/ln(5) once (512KB each),
// then the main kernel is elementwise: sum_{i<j} G_alpha * exp2(G_betap * log2(|ti-tj|+1e-10)).

#define NJ   16     // j-columns per CTA
#define GPAD 17     // smem row stride for G tiles [e][j] (conflict-free)

__device__ float g_alpha[256 * 512];   // [c][e]
__device__ float g_betap[256 * 512];   // [c][e], pre-scaled by -1/ln(5)

// ---------------- Precompute: two 256x512x64 GEMMs into tables ----------------
__global__ __launch_bounds__(256)
void precompute_kernel(const float* __restrict__ a_inter,    // [512,64]
                       const float* __restrict__ a_concept,  // [256,64]
                       const float* __restrict__ b_inter,    // [512,64]
                       const float* __restrict__ b_concept)  // [256,64]
{
    __shared__ float ai[64], bi[64];
    const int e = blockIdx.x;     // 0..511 (inter index)
    const int c = threadIdx.x;    // 0..255 (concept index)
    if (threadIdx.x < 64) {
        ai[threadIdx.x] = a_inter[e * 64 + threadIdx.x];
        bi[threadIdx.x] = b_inter[e * 64 + threadIdx.x];
    }
    __syncthreads();

    const float4* ac = (const float4*)(a_concept + c * 64);
    const float4* bc = (const float4*)(b_concept + c * 64);
    float sa = 0.f, sb = 0.f;
    #pragma unroll
    for (int q = 0; q < 16; q++) {
        float4 av = ac[q];
        float4 bv = bc[q];
        sa = fmaf(av.x, ai[4*q+0], sa); sa = fmaf(av.y, ai[4*q+1], sa);
        sa = fmaf(av.z, ai[4*q+2], sa); sa = fmaf(av.w, ai[4*q+3], sa);
        sb = fmaf(bv.x, bi[4*q+0], sb); sb = fmaf(bv.y, bi[4*q+1], sb);
        sb = fmaf(bv.z, bi[4*q+2], sb); sb = fmaf(bv.w, bi[4*q+3], sb);
    }
    g_alpha[c * 512 + e] = sa;
    float beta = fminf(fmaxf(sb + 1.0f, 0.0f), 10.0f);
    g_betap[c * 512 + e] = -beta * 0.62133497f;   // -beta / ln(5)
}

// ---------------- Main: causal elementwise sum via table gathers ----------------
__global__ __launch_bounds__(256)
void hawkes_main(const int* __restrict__ concept_seq,      // [32,1024]
                 const int* __restrict__ question_seq,     // [32,1024]
                 const int* __restrict__ correctness_seq,  // [32,1024]
                 const int* __restrict__ time_seq,         // [32,1024]
                 const float* __restrict__ q_bias,         // [10000]
                 const float* __restrict__ c_bias,         // [256]
                 float* __restrict__ out)                  // [32,1023]
{
    constexpr int SEQ = 1024;
    extern __shared__ float sm[];
    float* Ga   = sm;                        // [512][GPAD]
    float* Gb   = Ga + 512 * GPAD;           // [512][GPAD]
    float* ts   = Gb + 512 * GPAD;           // [1024]
    int*   es   = (int*)(ts + SEQ);          // [1024]
    float* jred = (float*)(es + SEQ);        // [NJ]

    const int b   = blockIdx.y;
    const int j0  = blockIdx.x * NJ;
    const int tid = threadIdx.x;
    const int tj  = tid & (NJ - 1);          // j lane 0..15
    const int si  = tid >> 4;                // i slot 0..15

    // Stage times (as float) and inter indices for the whole sequence
    for (int i = tid; i < SEQ; i += 256) {
        int g = b * SEQ + i;
        ts[i] = (float)time_seq[g];
        es[i] = concept_seq[g] + correctness_seq[g] * 256;
    }
    if (tid < NJ) jred[tid] = 0.0f;
    __syncthreads();

    // Gather G columns for this CTA's NJ concepts: Gs[e][jl] <- G[c_j][e]
    // (coalesced 2KB row reads from L2; conflict-free smem writes via GPAD=17)
    for (int idx = tid; idx < 128 * NJ; idx += 256) {
        int jl = idx >> 7;                   // 0..15
        int e4 = idx & 127;                  // float4 index within 512-row
        int cj = concept_seq[b * SEQ + j0 + jl];
        float4 va = *(const float4*)(g_alpha + cj * 512 + e4 * 4);
        float4 vb = *(const float4*)(g_betap + cj * 512 + e4 * 4);
        int e = e4 * 4;
        Ga[(e+0)*GPAD + jl] = va.x; Ga[(e+1)*GPAD + jl] = va.y;
        Ga[(e+2)*GPAD + jl] = va.z; Ga[(e+3)*GPAD + jl] = va.w;
        Gb[(e+0)*GPAD + jl] = vb.x; Gb[(e+1)*GPAD + jl] = vb.y;
        Gb[(e+2)*GPAD + jl] = vb.z; Gb[(e+3)*GPAD + jl] = vb.w;
    }
    __syncthreads();

    const int jg   = j0 + tj;
    const float tjv = ts[jg];
    const int iend = j0 + NJ;                // i < jg predicated inside
    float jsum = 0.0f;

    #pragma unroll 4
    for (int i = si; i < iend; i += 16) {
        int   e  = es[i];                    // uniform per half-warp -> broadcast
        float ti = ts[i];
        float ga = Ga[e * GPAD + tj];
        float gb = Gb[e * GPAD + tj];
        float dt = fabsf(ti - tjv);
        float lg = __log2f(dt + 1e-10f);
        float ex = exp2f(gb * lg);           // = exp(-beta * log5(dt))
        jsum += (i < jg) ? ga * ex : 0.0f;
    }

    // Reduce the 16 i-slots per j: fold pairs via shuffle, then smem atomics
    jsum += __shfl_down_sync(0xffffffffu, jsum, 16);
    if ((tid & 31) < 16) atomicAdd(&jred[tj], jsum);
    __syncthreads();

    // Epilogue: bias + sigmoid; output drops j=0
    if (tid < NJ) {
        int j = j0 + tid;
        if (j > 0) {
            float x = q_bias[question_seq[b * SEQ + j]]
                    + c_bias[concept_seq[b * SEQ + j]]
                    + jred[tid];
            out[b * (SEQ - 1) + (j - 1)] = 1.0f / (1.0f + __expf(-x));
        }
    }
}

extern "C" void kernel_launch(void* const* d_in, const int* in_sizes, int n_in,
                              void* d_out, int out_size)
{
    (void)in_sizes; (void)n_in; (void)out_size;
    const int*   concept_seq     = (const int*)  d_in[0];
    const int*   question_seq    = (const int*)  d_in[1];
    const int*   correctness_seq = (const int*)  d_in[2];
    const int*   time_seq        = (const int*)  d_in[3];
    const float* a_inter         = (const float*)d_in[4];
    const float* a_concept       = (const float*)d_in[5];
    const float* b_inter         = (const float*)d_in[6];
    const float* b_concept       = (const float*)d_in[7];
    const float* q_bias          = (const float*)d_in[8];
    const float* c_bias          = (const float*)d_in[9];
    float* out = (float*)d_out;

    precompute_kernel<<<512, 256>>>(a_inter, a_concept, b_inter, b_concept);

    const int smem_bytes = (2 * 512 * GPAD + 1024 + 1024 + NJ) * (int)sizeof(float);
    cudaFuncSetAttribute(hawkes_main,
                         cudaFuncAttributeMaxDynamicSharedMemorySize, smem_bytes);
    dim3 grid(1024 / NJ, 32);   // (j-tiles, batches)
    hawkes_main<<<grid, 256, smem_bytes>>>(
        concept_seq, question_seq, correctness_seq, time_seq,
        q_bias, c_bias, out);
}